// round 9
// baseline (speedup 1.0000x reference)
#include <cuda_runtime.h>
#include <cuda_bf16.h>
#include <cstdint>

// ---------------- Problem constants ----------------
#define NNODES 50000
#define NEDGES 800000
#define ETOT   (NEDGES + NNODES)   // + self loops
#define NBLK   ((NNODES + 1023) / 1024)   // 49 scan blocks

// ---------------- Device scratch (no allocs allowed) ----------------
__device__ float g_xl[NNODES * 128];
__device__ float g_xr[NNODES * 128];
__device__ float g_h[NNODES * 128];      // layer activation ping buffer
__device__ int   g_src[ETOT];
__device__ int   g_dst[ETOT];
__device__ int   g_csrc[ETOT];           // src ids sorted by dst (CSR)
__device__ int   g_rowptr[NNODES + 1];
__device__ int   g_deg[NNODES];
__device__ int   g_cnt[NNODES];
__device__ int   g_bsum[NBLK];
__device__ int   g_boff[NBLK];
__device__ int   g_is64;

// ---------------- packed f32x2 helpers (SASS FFMA2 on sm_103) ----------------
typedef unsigned long long u64;

__device__ __forceinline__ u64 pack2(float x) {
    u64 d;
    asm("mov.b64 %0, {%1, %1};" : "=l"(d) : "r"(__float_as_uint(x)));
    return d;
}
__device__ __forceinline__ void fma2(u64& d, u64 a, u64 b) {
    asm("fma.rn.f32x2 %0, %1, %2, %0;" : "+l"(d) : "l"(a), "l"(b));
}

// ---------------- zero counters + parallel dtype detect ----------------
__global__ void prep_kernel(const int* ei) {
    int i = blockIdx.x * blockDim.x + threadIdx.x;
    if (i < NNODES) { g_deg[i] = 0; g_cnt[i] = 0; }
    if (blockIdx.x == 0 && threadIdx.x < 32) {
        int nz = 0;
#pragma unroll
        for (int q = 0; q < 4; q++)
            nz |= ei[2 * (threadIdx.x * 4 + q) + 1];
        unsigned any = __ballot_sync(0xffffffffu, nz != 0);
        if (threadIdx.x == 0) g_is64 = (any == 0u);
    }
}

__global__ void canon_hist_kernel(const void* ei) {
    int i = blockIdx.x * blockDim.x + threadIdx.x;
    if (i >= ETOT) return;
    int s, d;
    if (i < NEDGES) {
        if (g_is64) {
            const long long* p = (const long long*)ei;
            s = (int)p[i];
            d = (int)p[NEDGES + i];
        } else {
            const int* p = (const int*)ei;
            s = p[i];
            d = p[NEDGES + i];
        }
    } else {
        s = d = i - NEDGES;
    }
    g_src[i] = s;
    g_dst[i] = d;
    atomicAdd(&g_deg[d], 1);
}

__global__ void scan1_kernel() {
    __shared__ int wtot[32];
    const int t = threadIdx.x, lane = t & 31, wid = t >> 5;
    const int gi = blockIdx.x * 1024 + t;
    int v = (gi < NNODES) ? g_deg[gi] : 0;
    int incl = v;
#pragma unroll
    for (int off = 1; off < 32; off <<= 1) {
        int x = __shfl_up_sync(0xffffffffu, incl, off);
        if (lane >= off) incl += x;
    }
    if (lane == 31) wtot[wid] = incl;
    __syncthreads();
    if (wid == 0) {
        int wv = wtot[lane];
        int wi = wv;
#pragma unroll
        for (int off = 1; off < 32; off <<= 1) {
            int x = __shfl_up_sync(0xffffffffu, wi, off);
            if (lane >= off) wi += x;
        }
        wtot[lane] = wi - wv;
    }
    __syncthreads();
    int excl = wtot[wid] + incl - v;
    if (gi < NNODES) g_rowptr[gi] = excl;
    if (t == 1023) g_bsum[blockIdx.x] = excl + v;
}

__global__ void scan2_kernel() {
    if (threadIdx.x == 0) {
        int t = 0;
#pragma unroll
        for (int ib = 0; ib < NBLK; ib++) {
            int v = g_bsum[ib];
            g_boff[ib] = t;
            t += v;
        }
        g_rowptr[NNODES] = t;
    }
}

__global__ void scan3_kernel() {
    int gi = blockIdx.x * 1024 + threadIdx.x;
    if (gi < NNODES && blockIdx.x > 0) g_rowptr[gi] += g_boff[blockIdx.x];
}

__global__ void scatter_kernel() {
    int i = blockIdx.x * blockDim.x + threadIdx.x;
    if (i >= ETOT) return;
    int d = g_dst[i];
    int pos = g_rowptr[d] + atomicAdd(&g_cnt[d], 1);
    g_csrc[pos] = g_src[i];
}

// ---------------- Dual GEMM (FFMA2): Yl = X@Wl, Yr = X@Wr ----------------
template <int COLS>
__global__ void gemm_dual_kernel(const float* __restrict__ X,
                                 const float* __restrict__ Wl,
                                 const float* __restrict__ Wr,
                                 float* __restrict__ Yl,
                                 float* __restrict__ Yr) {
    constexpr int TM = 64;
    constexpr int CG = COLS / 4;          // float4 column groups
    constexpr int RG = 256 / CG;          // row groups
    constexpr int RPT = TM / RG;          // rows per thread (8 or 4)
    constexpr int RF4 = RPT / 4;          // float4 X chunks per thread (2 or 1)

    __shared__ float  Xs[32][68];         // transposed: [k][row]
    __shared__ float4 Wsl[32][CG];
    __shared__ float4 Wsr[32][CG];

    const int tid = threadIdx.x;
    const int cg = tid % CG;
    const int rg = tid / CG;
    const int row0 = blockIdx.x * TM;

    // packed f32x2 accumulators: [row][pair], pair0 = cols (cg*4, cg*4+1)
    u64 accl[RPT][2], accr[RPT][2];
#pragma unroll
    for (int r = 0; r < RPT; r++) {
        accl[r][0] = 0ull; accl[r][1] = 0ull;
        accr[r][0] = 0ull; accr[r][1] = 0ull;
    }

    for (int k0 = 0; k0 < 128; k0 += 32) {
        __syncthreads();
#pragma unroll
        for (int u = tid; u < TM * 8; u += 256) {
            int r = u & 63, k4 = u >> 6;
            float4 xv = make_float4(0.f, 0.f, 0.f, 0.f);
            int gr = row0 + r;
            if (gr < NNODES)
                xv = *(const float4*)&X[gr * 128 + k0 + k4 * 4];
            Xs[k4 * 4 + 0][r] = xv.x;
            Xs[k4 * 4 + 1][r] = xv.y;
            Xs[k4 * 4 + 2][r] = xv.z;
            Xs[k4 * 4 + 3][r] = xv.w;
        }
#pragma unroll
        for (int u = tid; u < 32 * CG; u += 256) {
            int k = u / CG, c = u % CG;
            Wsl[k][c] = ((const float4*)Wl)[(k0 + k) * CG + c];
            Wsr[k][c] = ((const float4*)Wr)[(k0 + k) * CG + c];
        }
        __syncthreads();

#pragma unroll 8
        for (int k = 0; k < 32; k++) {
            ulonglong2 wl = *(const ulonglong2*)&Wsl[k][cg];
            ulonglong2 wr = *(const ulonglong2*)&Wsr[k][cg];
            const float4* xrow = (const float4*)&Xs[k][0];
#pragma unroll
            for (int q = 0; q < RF4; q++) {
                float4 xv = xrow[rg * RF4 + q];
#pragma unroll
                for (int j = 0; j < 4; j++) {
                    float x = (j == 0) ? xv.x : (j == 1) ? xv.y : (j == 2) ? xv.z : xv.w;
                    int r = q * 4 + j;
                    u64 xx = pack2(x);
                    fma2(accl[r][0], xx, wl.x);
                    fma2(accl[r][1], xx, wl.y);
                    fma2(accr[r][0], xx, wr.x);
                    fma2(accr[r][1], xx, wr.y);
                }
            }
        }
    }

#pragma unroll
    for (int r = 0; r < RPT; r++) {
        int gr = row0 + rg * RPT + r;
        if (gr < NNODES) {
            u64* ol = (u64*)&Yl[gr * COLS + cg * 4];
            u64* orr = (u64*)&Yr[gr * COLS + cg * 4];
            ol[0] = accl[r][0]; ol[1] = accl[r][1];
            orr[0] = accr[r][0]; orr[1] = accr[r][1];
        }
    }
}

// ---------------- CSR edge pass: 2-edge software-pipelined ----------------
template <int ROWF4>
__global__ void csr_edge_kernel(const float* __restrict__ att,
                                const float* __restrict__ bias,
                                float* __restrict__ out) {
    constexpr int NPW = 32 / ROWF4;
    int gwarp = (blockIdx.x * blockDim.x + threadIdx.x) >> 5;
    int lane = threadIdx.x & 31;
    int sub = lane / ROWF4;
    int l = lane % ROWF4;
    int d = gwarp * NPW + sub;
    if (d >= NNODES) return;

    const float4* xl4 = (const float4*)g_xl;
    float4 b = ((const float4*)g_xr)[d * ROWF4 + l];
    float4 w = ((const float4*)att)[l];

    float4 acc = make_float4(0.f, 0.f, 0.f, 0.f);
    float den = 0.f;

    int i = g_rowptr[d];
    const int end = g_rowptr[d + 1];

    int s0 = g_csrc[i];
    int s1 = (i + 1 < end) ? g_csrc[i + 1] : 0;
    float4 a0 = xl4[s0 * ROWF4 + l];
    float4 a1 = xl4[s1 * ROWF4 + l];

    while (i < end) {
        const int ni = i + 2;
        int t0 = (ni < end) ? g_csrc[ni] : 0;
        int t1 = (ni + 1 < end) ? g_csrc[ni + 1] : 0;
        float4 n0 = xl4[t0 * ROWF4 + l];
        float4 n1 = xl4[t1 * ROWF4 + l];

        float vx0 = a0.x + b.x, vy0 = a0.y + b.y, vz0 = a0.z + b.z, vw0 = a0.w + b.w;
        float vx1 = a1.x + b.x, vy1 = a1.y + b.y, vz1 = a1.z + b.z, vw1 = a1.w + b.w;
        vx0 = vx0 > 0.f ? vx0 : 0.2f * vx0;  vx1 = vx1 > 0.f ? vx1 : 0.2f * vx1;
        vy0 = vy0 > 0.f ? vy0 : 0.2f * vy0;  vy1 = vy1 > 0.f ? vy1 : 0.2f * vy1;
        vz0 = vz0 > 0.f ? vz0 : 0.2f * vz0;  vz1 = vz1 > 0.f ? vz1 : 0.2f * vz1;
        vw0 = vw0 > 0.f ? vw0 : 0.2f * vw0;  vw1 = vw1 > 0.f ? vw1 : 0.2f * vw1;
        float p0 = vx0 * w.x + vy0 * w.y + vz0 * w.z + vw0 * w.w;
        float p1 = vx1 * w.x + vy1 * w.y + vz1 * w.z + vw1 * w.w;

        p0 += __shfl_xor_sync(0xffffffffu, p0, 8);
        p1 += __shfl_xor_sync(0xffffffffu, p1, 8);
        p0 += __shfl_xor_sync(0xffffffffu, p0, 4);
        p1 += __shfl_xor_sync(0xffffffffu, p1, 4);
        p0 += __shfl_xor_sync(0xffffffffu, p0, 2);
        p1 += __shfl_xor_sync(0xffffffffu, p1, 2);
        p0 += __shfl_xor_sync(0xffffffffu, p0, 1);
        p1 += __shfl_xor_sync(0xffffffffu, p1, 1);

        float ex0 = __expf(p0);
        float ex1 = (i + 1 < end) ? __expf(p1) : 0.f;

        acc.x += ex0 * a0.x + ex1 * a1.x;
        acc.y += ex0 * a0.y + ex1 * a1.y;
        acc.z += ex0 * a0.z + ex1 * a1.z;
        acc.w += ex0 * a0.w + ex1 * a1.w;
        den += ex0 + ex1;

        a0 = n0; a1 = n1;
        i = ni;
    }

    float4 bi = ((const float4*)bias)[l];
    float inv = 1.0f / den;
    float4 o;
    o.x = acc.x * inv + bi.x;
    o.y = acc.y * inv + bi.y;
    o.z = acc.z * inv + bi.z;
    o.w = acc.w * inv + bi.w;
    o.x = o.x > 0.f ? o.x : (__expf(o.x) - 1.f);
    o.y = o.y > 0.f ? o.y : (__expf(o.y) - 1.f);
    o.z = o.z > 0.f ? o.z : (__expf(o.z) - 1.f);
    o.w = o.w > 0.f ? o.w : (__expf(o.w) - 1.f);
    ((float4*)out)[d * ROWF4 + l] = o;
}

// ---------------- Layer driver ----------------
template <int COLS>
static void run_layer(const float* in, const float* Wl, const float* Wr,
                      const float* att, const float* bias, float* out,
                      float* d_xl, float* d_xr) {
    constexpr int ROWF4 = COLS / 4;
    constexpr int NPW = 32 / ROWF4;
    gemm_dual_kernel<COLS><<<(NNODES + 63) / 64, 256>>>(in, Wl, Wr, d_xl, d_xr);
    int nwarps = (NNODES + NPW - 1) / NPW;
    csr_edge_kernel<ROWF4><<<(nwarps * 32 + 255) / 256, 256>>>(att, bias, out);
}

// ---------------- Entry point ----------------
extern "C" void kernel_launch(void* const* d_in, const int* in_sizes, int n_in,
                              void* d_out, int out_size) {
    const float* x    = (const float*)d_in[0];
    const void*  ei   = d_in[1];
    const float* W1l  = (const float*)d_in[2];
    const float* W1r  = (const float*)d_in[3];
    const float* att1 = (const float*)d_in[4];
    const float* b1   = (const float*)d_in[5];
    const float* W2l  = (const float*)d_in[6];
    const float* W2r  = (const float*)d_in[7];
    const float* att2 = (const float*)d_in[8];
    const float* b2   = (const float*)d_in[9];
    const float* W3l  = (const float*)d_in[10];
    const float* W3r  = (const float*)d_in[11];
    const float* att3 = (const float*)d_in[12];
    const float* b3   = (const float*)d_in[13];
    float* out = (float*)d_out;

    float *d_xl, *d_xr, *d_h;
    cudaGetSymbolAddress((void**)&d_xl, g_xl);
    cudaGetSymbolAddress((void**)&d_xr, g_xr);
    cudaGetSymbolAddress((void**)&d_h,  g_h);

    // one-time preprocessing: dtype canon + CSR build (dst-sorted)
    prep_kernel<<<(NNODES + 255) / 256, 256>>>((const int*)ei);
    canon_hist_kernel<<<(ETOT + 255) / 256, 256>>>(ei);
    scan1_kernel<<<NBLK, 1024>>>();
    scan2_kernel<<<1, 32>>>();
    scan3_kernel<<<NBLK, 1024>>>();
    scatter_kernel<<<(ETOT + 255) / 256, 256>>>();

    run_layer<128>(x,   W1l, W1r, att1, b1, d_h, d_xl, d_xr);
    run_layer<128>(d_h, W2l, W2r, att2, b2, d_h, d_xl, d_xr);
    run_layer<64>(d_h,  W3l, W3r, att3, b3, out, d_xl, d_xr);
}